// round 2
// baseline (speedup 1.0000x reference)
#include <cuda_runtime.h>
#include <math.h>

// Problem constants
#define BSZ   4096
#define FDIM  2048
#define KC    64
#define DD    8
#define NTOT  1024   // K * 2 * D
#define NPAIR 2080   // K*(K+1)/2
#define EPSV  1e-23f

// Scratch (static device allocations — allowed)
__device__ float g_theta[BSZ * NTOT];   // holds theta; after head kernel slot[8..15] holds Z
__device__ float g_lvbox[BSZ * KC];

// ---------------------------------------------------------------------------
// Kernel 1: theta[b, n] = sum_f features[b,f] * Wp[n>>4, f, n&15] + bp[n]
// Tiled fp32 GEMM: 128x64 block tile, BK=16, 256 threads, 8x4 per-thread tile.
// ---------------------------------------------------------------------------
__global__ void __launch_bounds__(256) gemm_kernel(const float* __restrict__ A,
                                                   const float* __restrict__ Wp,
                                                   const float* __restrict__ bp) {
    __shared__ float As[16][132];   // [k][m], padded (132*4 bytes, 16B-aligned rows)
    __shared__ float Bs[16][64];    // [k][n]

    const int tid  = threadIdx.x;
    const int tx   = tid & 15;      // n direction (16)
    const int ty   = tid >> 4;      // m direction (16)
    const int row0 = blockIdx.y * 128;
    const int col0 = blockIdx.x * 64;

    // A tile load mapping: thread -> row ar, two float4s at cols ac*4, (ac+1)*4
    const int ar = tid >> 1;
    const int ac = (tid & 1) * 2;

    // B tile load mapping: thread -> k-row krow, 4 consecutive n at nc
    const int krow = tid >> 4;
    const int nc   = (tid & 15) * 4;
    const int n_g  = col0 + nc;
    const int kbox = n_g >> 4;      // which K-slice of Wp
    const int ddof = n_g & 15;      // offset within 2D chunk (multiple of 4)

    float acc[8][4];
#pragma unroll
    for (int i = 0; i < 8; i++)
#pragma unroll
        for (int j = 0; j < 4; j++) acc[i][j] = 0.0f;

    for (int kk = 0; kk < FDIM; kk += 16) {
        // load A tile (128 x 16)
        {
            const float4 v0 = *reinterpret_cast<const float4*>(
                &A[(size_t)(row0 + ar) * FDIM + kk + ac * 4]);
            const float4 v1 = *reinterpret_cast<const float4*>(
                &A[(size_t)(row0 + ar) * FDIM + kk + (ac + 1) * 4]);
            As[ac * 4 + 0][ar] = v0.x;
            As[ac * 4 + 1][ar] = v0.y;
            As[ac * 4 + 2][ar] = v0.z;
            As[ac * 4 + 3][ar] = v0.w;
            As[(ac + 1) * 4 + 0][ar] = v1.x;
            As[(ac + 1) * 4 + 1][ar] = v1.y;
            As[(ac + 1) * 4 + 2][ar] = v1.z;
            As[(ac + 1) * 4 + 3][ar] = v1.w;
        }
        // load B tile (16 x 64) from Wp with n -> (k, dd) mapping
        {
            const float4 v = *reinterpret_cast<const float4*>(
                &Wp[((size_t)kbox * FDIM + (kk + krow)) * 16 + ddof]);
            *reinterpret_cast<float4*>(&Bs[krow][nc]) = v;
        }
        __syncthreads();

#pragma unroll
        for (int k = 0; k < 16; k++) {
            const float4 a0 = *reinterpret_cast<const float4*>(&As[k][ty * 8]);
            const float4 a1 = *reinterpret_cast<const float4*>(&As[k][ty * 8 + 4]);
            const float4 bv = *reinterpret_cast<const float4*>(&Bs[k][tx * 4]);
            const float am[8] = {a0.x, a0.y, a0.z, a0.w, a1.x, a1.y, a1.z, a1.w};
            const float bn[4] = {bv.x, bv.y, bv.z, bv.w};
#pragma unroll
            for (int i = 0; i < 8; i++)
#pragma unroll
                for (int j = 0; j < 4; j++)
                    acc[i][j] = fmaf(am[i], bn[j], acc[i][j]);
        }
        __syncthreads();
    }

    // epilogue: add bias, store theta
#pragma unroll
    for (int i = 0; i < 8; i++) {
        const int m = row0 + ty * 8 + i;
        float* crow = &g_theta[(size_t)m * NTOT + col0 + tx * 4];
#pragma unroll
        for (int j = 0; j < 4; j++)
            crow[j] = acc[i][j] + bp[col0 + tx * 4 + j];
    }
}

// ---------------------------------------------------------------------------
// Kernel 2: per (b,k): z/Z, concept_probs, lv_box. Writes Z back into theta.
// ---------------------------------------------------------------------------
__device__ __forceinline__ float softplus_acc(float x) {
    return fmaxf(x, 0.0f) + log1pf(expf(-fabsf(x)));
}

__global__ void __launch_bounds__(256) head_kernel(const float* __restrict__ Wprob,
                                                   const float* __restrict__ bprob,
                                                   float* __restrict__ out_concept) {
    const int idx = blockIdx.x * blockDim.x + threadIdx.x;  // b*64 + k
    if (idx >= BSZ * KC) return;
    const int k = idx & 63;

    float* th = &g_theta[(size_t)idx * 16];

    float z[8], Z[8];
#pragma unroll
    for (int d = 0; d < 8; d++) {
        z[d] = th[d];
        Z[d] = z[d] + softplus_acc(th[8 + d]);
        th[8 + d] = Z[d];   // store Z in place
    }

    // concept logits
    float logit = bprob[k];
#pragma unroll
    for (int d = 0; d < 8; d++) {
        logit = fmaf(z[d], Wprob[k * 16 + d], logit);
        logit = fmaf(Z[d], Wprob[k * 16 + 8 + d], logit);
    }
    out_concept[idx] = 1.0f / (1.0f + expf(-logit));

    // lv_box: sum_d log(max(softplus(2*(Z-z))/2, EPS))
    float lvb = 0.0f;
#pragma unroll
    for (int d = 0; d < 8; d++) {
        const float s    = Z[d] - z[d];
        const float side = 0.5f * softplus_acc(2.0f * s);
        lvb += logf(fmaxf(side, EPSV));
    }
    g_lvbox[idx] = lvb;
}

// ---------------------------------------------------------------------------
// Kernel 3: one block per b. Computes lv_int on the (i<=j) triangle (symmetric),
// then writes cond[b,i,j] for all (i,j), plus the rel/box dot products and the
// final task_prob — all with deterministic in-block reductions.
// ---------------------------------------------------------------------------
__device__ __forceinline__ int tri_S(int i) { return (i * (129 - i)) >> 1; }

__global__ void __launch_bounds__(256) pair_kernel(const float* __restrict__ Wrel,
                                                   const float* __restrict__ Wbox,
                                                   const float* __restrict__ bbox,
                                                   const float* __restrict__ brel,
                                                   const float* __restrict__ concept,
                                                   float* __restrict__ out_cond,
                                                   float* __restrict__ out_task) {
    __shared__ float zsh[KC * 9];     // padded stride-9 for conflict-free access
    __shared__ float Zsh[KC * 9];
    __shared__ float lvb_sh[KC];
    __shared__ float p_sh[KC];
    __shared__ float wrel_sh[KC * KC];
    __shared__ float wbox_sh[KC * 16];
    __shared__ float lvint_sh[NPAIR];
    __shared__ float red[256];

    const int b   = blockIdx.x;
    const int tid = threadIdx.x;
    const float* thb = &g_theta[(size_t)b * NTOT];

    // -------- load phase --------
    for (int idx = tid; idx < KC * DD; idx += 256) {
        const int k = idx >> 3, d = idx & 7;
        zsh[k * 9 + d] = thb[k * 16 + d];
        Zsh[k * 9 + d] = thb[k * 16 + 8 + d];
    }
    for (int idx = tid; idx < KC; idx += 256) {
        lvb_sh[idx] = g_lvbox[b * KC + idx];
        p_sh[idx]   = concept[b * KC + idx];
    }
    for (int idx = tid; idx < KC * KC; idx += 256) wrel_sh[idx] = Wrel[idx];
    for (int idx = tid; idx < KC * 16; idx += 256) wbox_sh[idx] = Wbox[idx];
    __syncthreads();

    // -------- pass 1: lv_int over upper triangle --------
    for (int q = tid; q < NPAIR; q += 256) {
        // decode i from triangular index
        int i = (int)((129.0f - sqrtf((float)(16641 - 8 * q))) * 0.5f);
        while (i < 63 && tri_S(i + 1) <= q) i++;
        while (i > 0 && tri_S(i) > q) i--;
        const int j = i + (q - tri_S(i));

        float prod = 1.0f;
#pragma unroll
        for (int d = 0; d < 8; d++) {
            const float zi = zsh[i * 9 + d], zj = zsh[j * 9 + d];
            const float Zi = Zsh[i * 9 + d], Zj = Zsh[j * 9 + d];

            // z_int = max + t*log1p(exp(-|dz|/t)), t = 0.1  (the extra max is redundant)
            const float mz   = fmaxf(zi, zj);
            const float dz   = fabsf(zi - zj);
            const float zint = fmaf(0.1f, __logf(1.0f + __expf(-10.0f * dz)), mz);
            // Z_int = min - t*log1p(exp(-|dZ|/t))
            const float mZ   = fminf(Zi, Zj);
            const float dZ   = fabsf(Zi - Zj);
            const float Zint = fmaf(-0.1f, __logf(1.0f + __expf(-10.0f * dZ)), mZ);

            // side = softplus(2w)/2, clamped
            const float w2   = 2.0f * (Zint - zint);
            const float sp   = fmaxf(w2, 0.0f) + __logf(1.0f + __expf(-fabsf(w2)));
            const float side = fmaxf(0.5f * sp, EPSV);
            prod *= side;
        }
        // sum of logs == log of product; underflow -> -inf -> cond clips to 1e-6,
        // identical to reference after its own clip.
        lvint_sh[q] = __logf(prod);
    }
    __syncthreads();

    // -------- pass 2: cond + rel dot --------
    float accrel = 0.0f;
    for (int idx = tid; idx < KC * KC; idx += 256) {
        const int i = idx >> 6, j = idx & 63;
        const int a  = (i < j) ? i : j;
        const int bb = (i < j) ? j : i;
        const int q  = tri_S(a) + (bb - a);
        const float lv = lvint_sh[q] - lvb_sh[j];     // lv_box broadcast over axis j
        float c = __expf(lv);
        c = fminf(fmaxf(c, 1e-6f), 1.0f - 1e-6f);
        out_cond[(size_t)b * (KC * KC) + idx] = c;
        accrel = fmaf(c, wrel_sh[idx], accrel);
    }

    red[tid] = accrel;
    __syncthreads();
    for (int s = 128; s > 0; s >>= 1) {
        if (tid < s) red[tid] += red[tid + s];
        __syncthreads();
    }
    const float reldot = red[0];
    __syncthreads();

    // -------- box dot: sum_k p[k] * (z·Wbox_z + Z·Wbox_Z) --------
    if (tid < KC) {
        float s = 0.0f;
#pragma unroll
        for (int d = 0; d < 8; d++) {
            s = fmaf(zsh[tid * 9 + d], wbox_sh[tid * 16 + d], s);
            s = fmaf(Zsh[tid * 9 + d], wbox_sh[tid * 16 + 8 + d], s);
        }
        red[tid] = s * p_sh[tid];
    }
    __syncthreads();
    for (int s = 32; s > 0; s >>= 1) {
        if (tid < s) red[tid] += red[tid + s];
        __syncthreads();
    }

    if (tid == 0) {
        const float logit = red[0] + bbox[0] + reldot + brel[0];
        out_task[b] = 1.0f / (1.0f + expf(-logit));
    }
}

// ---------------------------------------------------------------------------
extern "C" void kernel_launch(void* const* d_in, const int* in_sizes, int n_in,
                              void* d_out, int out_size) {
    const float* features = (const float*)d_in[0];
    const float* Wp       = (const float*)d_in[1];
    const float* bp       = (const float*)d_in[2];
    const float* Wprob    = (const float*)d_in[3];
    const float* bprob    = (const float*)d_in[4];
    const float* Wbox     = (const float*)d_in[5];
    const float* bbox     = (const float*)d_in[6];
    const float* Wrel     = (const float*)d_in[7];
    const float* brel     = (const float*)d_in[8];

    float* out         = (float*)d_out;
    float* out_task    = out;                       // 4096
    float* out_concept = out + BSZ;                 // 262144
    float* out_cond    = out + BSZ + BSZ * KC;      // 16777216

    gemm_kernel<<<dim3(NTOT / 64, BSZ / 128), 256>>>(features, Wp, bp);
    head_kernel<<<(BSZ * KC) / 256, 256>>>(Wprob, bprob, out_concept);
    pair_kernel<<<BSZ, 256>>>(Wrel, Wbox, bbox, brel, out_concept, out_cond, out_task);
}

// round 5
// speedup vs baseline: 1.7416x; 1.7416x over previous
#include <cuda_runtime.h>
#include <cuda_bf16.h>
#include <math.h>
#include <stdint.h>

// ---------------- problem constants ----------------
#define BSZ   4096
#define FDIM  2048
#define KC    64
#define DD    8
#define NTOT  1024          // K * 2 * D
#define NPAIR 2080
#define EPSV  1e-23f

// ---------------- GEMM config (bf16x3 split, mma.sync HMMA) ----------------
#define KEXP    6144        // 3 * FDIM
#define TM      128
#define TN      128
#define BK      32
#define NS      (KEXP / BK) // 192
#define STAGES  3
#define GT      256
#define ROWP    40          // padded row length in bf16 elems (80B: 16B-aligned, conflict-free)
#define ATILE_B (TM * ROWP * 2)          // 10240 bytes
#define STAGE_B (2 * ATILE_B)            // 20480 bytes (A tile + B tile)
#define SMEM_B  (STAGES * STAGE_B)       // 61440 bytes

// ---------------- scratch ----------------
__device__ __nv_bfloat16 g_A[(size_t)BSZ * KEXP];   // [4096][6144]
__device__ __nv_bfloat16 g_Bm[(size_t)NTOT * KEXP]; // [1024][6144]
__device__ float g_theta[(size_t)BSZ * NTOT];
__device__ float g_lvbox[BSZ * KC];

// ---------------- PTX helpers ----------------
__device__ __forceinline__ uint32_t smem_u32(const void* p) {
    uint32_t a;
    asm("{ .reg .u64 t; cvta.to.shared.u64 t, %1; cvt.u32.u64 %0, t; }"
        : "=r"(a) : "l"(p));
    return a;
}
__device__ __forceinline__ void cp_async16(uint32_t d, const void* s) {
    asm volatile("cp.async.cg.shared.global [%0], [%1], 16;" :: "r"(d), "l"(s));
}
#define CP_COMMIT() asm volatile("cp.async.commit_group;" ::: "memory")
template <int N> __device__ __forceinline__ void cp_wait() {
    asm volatile("cp.async.wait_group %0;" :: "n"(N) : "memory");
}
__device__ __forceinline__ void ldsm4(uint32_t* r, uint32_t addr) {
    asm volatile("ldmatrix.sync.aligned.m8n8.x4.shared.b16 {%0,%1,%2,%3}, [%4];"
                 : "=r"(r[0]), "=r"(r[1]), "=r"(r[2]), "=r"(r[3]) : "r"(addr));
}
__device__ __forceinline__ void mma16816(float* c, const uint32_t* a, const uint32_t* b) {
    asm volatile(
        "mma.sync.aligned.m16n8k16.row.col.f32.bf16.bf16.f32 "
        "{%0,%1,%2,%3}, {%4,%5,%6,%7}, {%8,%9}, {%0,%1,%2,%3};"
        : "+f"(c[0]), "+f"(c[1]), "+f"(c[2]), "+f"(c[3])
        : "r"(a[0]), "r"(a[1]), "r"(a[2]), "r"(a[3]), "r"(b[0]), "r"(b[1]));
}

// ---------------------------------------------------------------------------
// Conversion kernels: build K-expanded bf16 operands.
// A'' = [Ahi | Alo | Ahi], B'' = [Whi | Whi | Wlo]  -> A''.B''^T ~= A.W^T (2^-17)
// ---------------------------------------------------------------------------
__global__ void __launch_bounds__(256) convA_kernel(const float* __restrict__ feat) {
    const int u = blockIdx.x * 256 + threadIdx.x;
    if (u >= BSZ * (FDIM / 4)) return;
    const int m = u >> 9;
    const int f = (u & 511) * 4;

    const float4 v = *reinterpret_cast<const float4*>(&feat[(size_t)m * FDIM + f]);
    union { __nv_bfloat16 h[4]; uint2 q; } Hi, Lo;
    Hi.h[0] = __float2bfloat16_rn(v.x);
    Hi.h[1] = __float2bfloat16_rn(v.y);
    Hi.h[2] = __float2bfloat16_rn(v.z);
    Hi.h[3] = __float2bfloat16_rn(v.w);
    Lo.h[0] = __float2bfloat16_rn(v.x - __bfloat162float(Hi.h[0]));
    Lo.h[1] = __float2bfloat16_rn(v.y - __bfloat162float(Hi.h[1]));
    Lo.h[2] = __float2bfloat16_rn(v.z - __bfloat162float(Hi.h[2]));
    Lo.h[3] = __float2bfloat16_rn(v.w - __bfloat162float(Hi.h[3]));

    __nv_bfloat16* row = &g_A[(size_t)m * KEXP];
    *reinterpret_cast<uint2*>(&row[f])            = Hi.q;
    *reinterpret_cast<uint2*>(&row[FDIM + f])     = Lo.q;
    *reinterpret_cast<uint2*>(&row[2 * FDIM + f]) = Hi.q;
}

__global__ void __launch_bounds__(256) convB_kernel(const float* __restrict__ Wp) {
    const int u = blockIdx.x * 256 + threadIdx.x;
    if (u >= NTOT * (FDIM / 4)) return;
    const int n = u >> 9;
    const int f = (u & 511) * 4;
    const int kbox = n >> 4;
    const int dd   = n & 15;

    union { __nv_bfloat16 h[4]; uint2 q; } Hi, Lo;
#pragma unroll
    for (int r = 0; r < 4; r++) {
        const float w = Wp[((size_t)kbox * FDIM + (f + r)) * 16 + dd];
        Hi.h[r] = __float2bfloat16_rn(w);
        Lo.h[r] = __float2bfloat16_rn(w - __bfloat162float(Hi.h[r]));
    }
    __nv_bfloat16* row = &g_Bm[(size_t)n * KEXP];
    *reinterpret_cast<uint2*>(&row[f])            = Hi.q;
    *reinterpret_cast<uint2*>(&row[FDIM + f])     = Hi.q;
    *reinterpret_cast<uint2*>(&row[2 * FDIM + f]) = Lo.q;
}

// ---------------------------------------------------------------------------
// HMMA GEMM: theta[4096][1024] = A''[4096][6144] . B''[1024][6144]^T + bp
// 128x128 CTA tile, BK=32, 3-stage cp.async ring, 8 warps of 64x32.
// ---------------------------------------------------------------------------
__device__ __forceinline__ void load_stage(int tid, int t, uint32_t sb,
                                           const __nv_bfloat16* Ab,
                                           const __nv_bfloat16* Bb) {
    const int k0 = t * BK;
    const uint32_t stage = sb + (uint32_t)((t % STAGES) * STAGE_B);
#pragma unroll
    for (int i = 0; i < 4; i++) {
        const int c = tid + i * GT;          // 0..1023 chunks of 16B
        if (c < 512) {                       // A: 128 rows x 4 chunks
            const int row = c >> 2, seg = c & 3;
            cp_async16(stage + (uint32_t)(row * (ROWP * 2) + seg * 16),
                       Ab + (size_t)row * KEXP + k0 + seg * 8);
        } else {                             // B: 128 rows x 4 chunks
            const int cc = c - 512;
            const int row = cc >> 2, seg = cc & 3;
            cp_async16(stage + (uint32_t)(ATILE_B + row * (ROWP * 2) + seg * 16),
                       Bb + (size_t)row * KEXP + k0 + seg * 8);
        }
    }
}

__global__ void __launch_bounds__(GT, 2) gemm_hmma(const float* __restrict__ bp) {
    extern __shared__ char smem[];
    const uint32_t sb = smem_u32(smem);
    const int tid  = threadIdx.x;
    const int wid  = tid >> 5;
    const int lane = tid & 31;
    const int row0 = blockIdx.y * TM;
    const int col0 = blockIdx.x * TN;
    const int m0w  = (wid >> 2) * 64;    // warp M offset
    const int n0w  = (wid & 3) * 32;     // warp N offset

    const __nv_bfloat16* Ab = g_A  + (size_t)row0 * KEXP;
    const __nv_bfloat16* Bb = g_Bm + (size_t)col0 * KEXP;

    float c[4][4][4];
#pragma unroll
    for (int mt = 0; mt < 4; mt++)
#pragma unroll
        for (int nt = 0; nt < 4; nt++)
#pragma unroll
            for (int r = 0; r < 4; r++) c[mt][nt][r] = 0.0f;

    // ldmatrix per-lane address components
    const int a_row = lane & 15;               // row within 16
    const int a_col = (lane >> 4) * 8;         // k half
    const int b_row = (lane & 7) + ((lane >> 4) & 1) * 8;  // n within 16
    const int b_col = ((lane >> 3) & 1) * 8;   // k half

    // prologue
    load_stage(tid, 0, sb, Ab, Bb); CP_COMMIT();
    load_stage(tid, 1, sb, Ab, Bb); CP_COMMIT();

    for (int s = 0; s < NS; s++) {
        cp_wait<STAGES - 2>();
        __syncthreads();
        if (s + STAGES - 1 < NS) load_stage(tid, s + STAGES - 1, sb, Ab, Bb);
        CP_COMMIT();

        const uint32_t sA = sb + (uint32_t)((s % STAGES) * STAGE_B);
        const uint32_t sBm = sA + ATILE_B;
#pragma unroll
        for (int kk = 0; kk < BK; kk += 16) {
            uint32_t afr[4][4];
            uint32_t bfr[4][2];
#pragma unroll
            for (int mt = 0; mt < 4; mt++)
                ldsm4(afr[mt],
                      sA + (uint32_t)(((m0w + mt * 16 + a_row) * ROWP + kk + a_col) * 2));
#pragma unroll
            for (int np = 0; np < 2; np++) {
                uint32_t q[4];
                ldsm4(q, sBm + (uint32_t)(((n0w + np * 16 + b_row) * ROWP + kk + b_col) * 2));
                bfr[np * 2 + 0][0] = q[0]; bfr[np * 2 + 0][1] = q[1];
                bfr[np * 2 + 1][0] = q[2]; bfr[np * 2 + 1][1] = q[3];
            }
#pragma unroll
            for (int mt = 0; mt < 4; mt++)
#pragma unroll
                for (int nt = 0; nt < 4; nt++)
                    mma16816(c[mt][nt], afr[mt], bfr[nt]);
        }
    }

    // epilogue: add bias, write theta
    const int er = lane >> 2;
    const int ec = (lane & 3) * 2;
#pragma unroll
    for (int mt = 0; mt < 4; mt++) {
#pragma unroll
        for (int nt = 0; nt < 4; nt++) {
            const int m = row0 + m0w + mt * 16 + er;
            const int n = col0 + n0w + nt * 8 + ec;
            const float b0 = __ldg(&bp[n]);
            const float b1 = __ldg(&bp[n + 1]);
            *reinterpret_cast<float2*>(&g_theta[(size_t)m * NTOT + n]) =
                make_float2(c[mt][nt][0] + b0, c[mt][nt][1] + b1);
            *reinterpret_cast<float2*>(&g_theta[(size_t)(m + 8) * NTOT + n]) =
                make_float2(c[mt][nt][2] + b0, c[mt][nt][3] + b1);
        }
    }
}

// ---------------------------------------------------------------------------
// Head kernel: per (b,k): z/Z, concept_probs, lv_box. Writes Z back into theta.
// ---------------------------------------------------------------------------
__device__ __forceinline__ float softplus_acc(float x) {
    return fmaxf(x, 0.0f) + log1pf(expf(-fabsf(x)));
}

__global__ void __launch_bounds__(256) head_kernel(const float* __restrict__ Wprob,
                                                   const float* __restrict__ bprob,
                                                   float* __restrict__ out_concept) {
    const int idx = blockIdx.x * blockDim.x + threadIdx.x;
    if (idx >= BSZ * KC) return;
    const int k = idx & 63;

    float* th = &g_theta[(size_t)idx * 16];
    float z[8], Z[8];
#pragma unroll
    for (int d = 0; d < 8; d++) {
        z[d] = th[d];
        Z[d] = z[d] + softplus_acc(th[8 + d]);
        th[8 + d] = Z[d];
    }

    float logit = bprob[k];
#pragma unroll
    for (int d = 0; d < 8; d++) {
        logit = fmaf(z[d], Wprob[k * 16 + d], logit);
        logit = fmaf(Z[d], Wprob[k * 16 + 8 + d], logit);
    }
    out_concept[idx] = 1.0f / (1.0f + expf(-logit));

    float lvb = 0.0f;
#pragma unroll
    for (int d = 0; d < 8; d++) {
        const float s    = Z[d] - z[d];
        const float side = 0.5f * softplus_acc(2.0f * s);
        lvb += logf(fmaxf(side, EPSV));
    }
    g_lvbox[idx] = lvb;
}

// ---------------------------------------------------------------------------
// Pair kernel: triangle lv_int, cond, fused head dots.
// ---------------------------------------------------------------------------
__device__ __forceinline__ int tri_S(int i) { return (i * (129 - i)) >> 1; }

__global__ void __launch_bounds__(256) pair_kernel(const float* __restrict__ Wrel,
                                                   const float* __restrict__ Wbox,
                                                   const float* __restrict__ bbox,
                                                   const float* __restrict__ brel,
                                                   const float* __restrict__ concept,
                                                   float* __restrict__ out_cond,
                                                   float* __restrict__ out_task) {
    __shared__ float zsh[KC * 9];
    __shared__ float Zsh[KC * 9];
    __shared__ float lvb_sh[KC];
    __shared__ float p_sh[KC];
    __shared__ float wrel_sh[KC * KC];
    __shared__ float wbox_sh[KC * 16];
    __shared__ float lvint_sh[NPAIR];
    __shared__ float red[256];

    const int b   = blockIdx.x;
    const int tid = threadIdx.x;
    const float* thb = &g_theta[(size_t)b * NTOT];

    for (int idx = tid; idx < KC * DD; idx += 256) {
        const int k = idx >> 3, d = idx & 7;
        zsh[k * 9 + d] = thb[k * 16 + d];
        Zsh[k * 9 + d] = thb[k * 16 + 8 + d];
    }
    for (int idx = tid; idx < KC; idx += 256) {
        lvb_sh[idx] = g_lvbox[b * KC + idx];
        p_sh[idx]   = concept[b * KC + idx];
    }
    for (int idx = tid; idx < KC * KC; idx += 256) wrel_sh[idx] = Wrel[idx];
    for (int idx = tid; idx < KC * 16; idx += 256) wbox_sh[idx] = Wbox[idx];
    __syncthreads();

    for (int q = tid; q < NPAIR; q += 256) {
        int i = (int)((129.0f - sqrtf((float)(16641 - 8 * q))) * 0.5f);
        while (i < 63 && tri_S(i + 1) <= q) i++;
        while (i > 0 && tri_S(i) > q) i--;
        const int j = i + (q - tri_S(i));

        float prod = 1.0f;
#pragma unroll
        for (int d = 0; d < 8; d++) {
            const float zi = zsh[i * 9 + d], zj = zsh[j * 9 + d];
            const float Zi = Zsh[i * 9 + d], Zj = Zsh[j * 9 + d];

            const float mz   = fmaxf(zi, zj);
            const float dz   = fabsf(zi - zj);
            const float zint = fmaf(0.1f, __logf(1.0f + __expf(-10.0f * dz)), mz);
            const float mZ   = fminf(Zi, Zj);
            const float dZ   = fabsf(Zi - Zj);
            const float Zint = fmaf(-0.1f, __logf(1.0f + __expf(-10.0f * dZ)), mZ);

            const float w2   = 2.0f * (Zint - zint);
            const float sp   = fmaxf(w2, 0.0f) + __logf(1.0f + __expf(-fabsf(w2)));
            const float side = fmaxf(0.5f * sp, EPSV);
            prod *= side;
        }
        lvint_sh[q] = __logf(prod);
    }
    __syncthreads();

    float accrel = 0.0f;
    for (int idx = tid; idx < KC * KC; idx += 256) {
        const int i = idx >> 6, j = idx & 63;
        const int a  = (i < j) ? i : j;
        const int bb = (i < j) ? j : i;
        const int q  = tri_S(a) + (bb - a);
        const float lv = lvint_sh[q] - lvb_sh[j];
        float cd = __expf(lv);
        cd = fminf(fmaxf(cd, 1e-6f), 1.0f - 1e-6f);
        out_cond[(size_t)b * (KC * KC) + idx] = cd;
        accrel = fmaf(cd, wrel_sh[idx], accrel);
    }

    red[tid] = accrel;
    __syncthreads();
    for (int s = 128; s > 0; s >>= 1) {
        if (tid < s) red[tid] += red[tid + s];
        __syncthreads();
    }
    const float reldot = red[0];
    __syncthreads();

    if (tid < KC) {
        float s = 0.0f;
#pragma unroll
        for (int d = 0; d < 8; d++) {
            s = fmaf(zsh[tid * 9 + d], wbox_sh[tid * 16 + d], s);
            s = fmaf(Zsh[tid * 9 + d], wbox_sh[tid * 16 + 8 + d], s);
        }
        red[tid] = s * p_sh[tid];
    }
    __syncthreads();
    for (int s = 32; s > 0; s >>= 1) {
        if (tid < s) red[tid] += red[tid + s];
        __syncthreads();
    }

    if (tid == 0) {
        const float logit = red[0] + bbox[0] + reldot + brel[0];
        out_task[b] = 1.0f / (1.0f + expf(-logit));
    }
}

// ---------------------------------------------------------------------------
extern "C" void kernel_launch(void* const* d_in, const int* in_sizes, int n_in,
                              void* d_out, int out_size) {
    const float* features = (const float*)d_in[0];
    const float* Wp       = (const float*)d_in[1];
    const float* bp       = (const float*)d_in[2];
    const float* Wprob    = (const float*)d_in[3];
    const float* bprob    = (const float*)d_in[4];
    const float* Wbox     = (const float*)d_in[5];
    const float* bbox     = (const float*)d_in[6];
    const float* Wrel     = (const float*)d_in[7];
    const float* brel     = (const float*)d_in[8];

    float* out         = (float*)d_out;
    float* out_task    = out;
    float* out_concept = out + BSZ;
    float* out_cond    = out + BSZ + BSZ * KC;

    static bool attr_done = false;
    if (!attr_done) {
        cudaFuncSetAttribute(gemm_hmma, cudaFuncAttributeMaxDynamicSharedMemorySize, SMEM_B);
        attr_done = true;
    }

    convA_kernel<<<(BSZ * (FDIM / 4) + 255) / 256, 256>>>(features);
    convB_kernel<<<(NTOT * (FDIM / 4) + 255) / 256, 256>>>(Wp);
    gemm_hmma<<<dim3(NTOT / TN, BSZ / TM), GT, SMEM_B>>>(bp);
    head_kernel<<<(BSZ * KC) / 256, 256>>>(Wprob, bprob, out_concept);
    pair_kernel<<<BSZ, 256>>>(Wrel, Wbox, bbox, brel, out_concept, out_cond, out_task);
}

// round 6
// speedup vs baseline: 1.8905x; 1.0855x over previous
#include <cuda_runtime.h>
#include <cuda_bf16.h>
#include <math.h>
#include <stdint.h>

// ---------------- problem constants ----------------
#define BSZ   4096
#define FDIM  2048
#define KC    64
#define DD    8
#define NTOT  1024          // K * 2 * D
#define NPAIR 2080
#define EPSV  1e-23f

// ---------------- GEMM config (bf16x3 split, mma.sync HMMA) ----------------
#define KEXP    6144        // logical K after 3-way split
#define KSTORE  4096        // physical K stored ([hi|lo]); region remap in loader
#define TM      128
#define TN      128
#define BK      32
#define NS      (KEXP / BK) // 192
#define STAGES  3
#define GT      256
#define ROWP    40          // padded row length in bf16 (80B, conflict-free ldmatrix)
#define ATILE_B (TM * ROWP * 2)          // 10240 bytes
#define STAGE_B (2 * ATILE_B)            // 20480 bytes
#define SMEM_B  (STAGES * STAGE_B)       // 61440 bytes

// ---------------- scratch ----------------
__device__ __nv_bfloat16 g_A[(size_t)BSZ * KSTORE];   // [4096][4096] = [Ahi|Alo]
__device__ __nv_bfloat16 g_Bm[(size_t)NTOT * KSTORE]; // [1024][4096] = [Whi|Wlo]
__device__ float g_theta[(size_t)BSZ * NTOT];

// ---------------- PTX helpers ----------------
__device__ __forceinline__ uint32_t smem_u32(const void* p) {
    uint32_t a;
    asm("{ .reg .u64 t; cvta.to.shared.u64 t, %1; cvt.u32.u64 %0, t; }"
        : "=r"(a) : "l"(p));
    return a;
}
__device__ __forceinline__ void cp_async16(uint32_t d, const void* s) {
    asm volatile("cp.async.cg.shared.global [%0], [%1], 16;" :: "r"(d), "l"(s));
}
#define CP_COMMIT() asm volatile("cp.async.commit_group;" ::: "memory")
template <int N> __device__ __forceinline__ void cp_wait() {
    asm volatile("cp.async.wait_group %0;" :: "n"(N) : "memory");
}
__device__ __forceinline__ void ldsm4(uint32_t* r, uint32_t addr) {
    asm volatile("ldmatrix.sync.aligned.m8n8.x4.shared.b16 {%0,%1,%2,%3}, [%4];"
                 : "=r"(r[0]), "=r"(r[1]), "=r"(r[2]), "=r"(r[3]) : "r"(addr));
}
__device__ __forceinline__ void mma16816(float* c, const uint32_t* a, const uint32_t* b) {
    asm volatile(
        "mma.sync.aligned.m16n8k16.row.col.f32.bf16.bf16.f32 "
        "{%0,%1,%2,%3}, {%4,%5,%6,%7}, {%8,%9}, {%0,%1,%2,%3};"
        : "+f"(c[0]), "+f"(c[1]), "+f"(c[2]), "+f"(c[3])
        : "r"(a[0]), "r"(a[1]), "r"(a[2]), "r"(a[3]), "r"(b[0]), "r"(b[1]));
}

// ---------------------------------------------------------------------------
// Conversion kernels: store only [hi | lo] halves; loader replays regions.
// Logical A'' = [Ahi | Alo | Ahi], B'' = [Whi | Whi | Wlo].
// ---------------------------------------------------------------------------
__global__ void __launch_bounds__(256) convA_kernel(const float* __restrict__ feat) {
    const int u = blockIdx.x * 256 + threadIdx.x;
    if (u >= BSZ * (FDIM / 4)) return;
    const int m = u >> 9;
    const int f = (u & 511) * 4;

    const float4 v = *reinterpret_cast<const float4*>(&feat[(size_t)m * FDIM + f]);
    union { __nv_bfloat16 h[4]; uint2 q; } Hi, Lo;
    Hi.h[0] = __float2bfloat16_rn(v.x);
    Hi.h[1] = __float2bfloat16_rn(v.y);
    Hi.h[2] = __float2bfloat16_rn(v.z);
    Hi.h[3] = __float2bfloat16_rn(v.w);
    Lo.h[0] = __float2bfloat16_rn(v.x - __bfloat162float(Hi.h[0]));
    Lo.h[1] = __float2bfloat16_rn(v.y - __bfloat162float(Hi.h[1]));
    Lo.h[2] = __float2bfloat16_rn(v.z - __bfloat162float(Hi.h[2]));
    Lo.h[3] = __float2bfloat16_rn(v.w - __bfloat162float(Hi.h[3]));

    __nv_bfloat16* row = &g_A[(size_t)m * KSTORE];
    *reinterpret_cast<uint2*>(&row[f])        = Hi.q;
    *reinterpret_cast<uint2*>(&row[FDIM + f]) = Lo.q;
}

__global__ void __launch_bounds__(256) convB_kernel(const float* __restrict__ Wp) {
    const int u = blockIdx.x * 256 + threadIdx.x;
    if (u >= NTOT * (FDIM / 4)) return;
    const int n = u >> 9;
    const int f = (u & 511) * 4;
    const int kbox = n >> 4;
    const int dd   = n & 15;

    union { __nv_bfloat16 h[4]; uint2 q; } Hi, Lo;
#pragma unroll
    for (int r = 0; r < 4; r++) {
        const float w = Wp[((size_t)kbox * FDIM + (f + r)) * 16 + dd];
        Hi.h[r] = __float2bfloat16_rn(w);
        Lo.h[r] = __float2bfloat16_rn(w - __bfloat162float(Hi.h[r]));
    }
    __nv_bfloat16* row = &g_Bm[(size_t)n * KSTORE];
    *reinterpret_cast<uint2*>(&row[f])        = Hi.q;
    *reinterpret_cast<uint2*>(&row[FDIM + f]) = Lo.q;
}

// ---------------------------------------------------------------------------
// HMMA GEMM: theta = A'' . B''^T + bp, 128x128 tile, BK=32, 3-stage cp.async.
// ---------------------------------------------------------------------------
__device__ __forceinline__ void load_stage(int tid, int t, uint32_t sb,
                                           const __nv_bfloat16* Ab,
                                           const __nv_bfloat16* Bb) {
    const int k0 = t * BK;
    const int ksA = (k0 < 2 * FDIM) ? k0 : k0 - 2 * FDIM;  // region 2 -> Ahi
    const int ksB = (k0 < FDIM) ? k0 : k0 - FDIM;          // regions 1,2 -> Whi,Wlo
    const uint32_t stage = sb + (uint32_t)((t % STAGES) * STAGE_B);
#pragma unroll
    for (int i = 0; i < 4; i++) {
        const int c = tid + i * GT;
        if (c < 512) {                       // A: 128 rows x 4 chunks of 16B
            const int row = c >> 2, seg = c & 3;
            cp_async16(stage + (uint32_t)(row * (ROWP * 2) + seg * 16),
                       Ab + (size_t)row * KSTORE + ksA + seg * 8);
        } else {                             // B: 128 rows x 4 chunks
            const int cc = c - 512;
            const int row = cc >> 2, seg = cc & 3;
            cp_async16(stage + (uint32_t)(ATILE_B + row * (ROWP * 2) + seg * 16),
                       Bb + (size_t)row * KSTORE + ksB + seg * 8);
        }
    }
}

__global__ void __launch_bounds__(GT, 2) gemm_hmma(const float* __restrict__ bp) {
    extern __shared__ char smem[];
    const uint32_t sb = smem_u32(smem);
    const int tid  = threadIdx.x;
    const int wid  = tid >> 5;
    const int lane = tid & 31;
    const int row0 = blockIdx.y * TM;
    const int col0 = blockIdx.x * TN;
    const int m0w  = (wid >> 2) * 64;
    const int n0w  = (wid & 3) * 32;

    const __nv_bfloat16* Ab = g_A  + (size_t)row0 * KSTORE;
    const __nv_bfloat16* Bb = g_Bm + (size_t)col0 * KSTORE;

    float c[4][4][4];
#pragma unroll
    for (int mt = 0; mt < 4; mt++)
#pragma unroll
        for (int nt = 0; nt < 4; nt++)
#pragma unroll
            for (int r = 0; r < 4; r++) c[mt][nt][r] = 0.0f;

    const int a_row = lane & 15;
    const int a_col = (lane >> 4) * 8;
    const int b_row = (lane & 7) + ((lane >> 4) & 1) * 8;
    const int b_col = ((lane >> 3) & 1) * 8;

    load_stage(tid, 0, sb, Ab, Bb); CP_COMMIT();
    load_stage(tid, 1, sb, Ab, Bb); CP_COMMIT();

    for (int s = 0; s < NS; s++) {
        cp_wait<STAGES - 2>();
        __syncthreads();
        if (s + STAGES - 1 < NS) load_stage(tid, s + STAGES - 1, sb, Ab, Bb);
        CP_COMMIT();

        const uint32_t sA  = sb + (uint32_t)((s % STAGES) * STAGE_B);
        const uint32_t sBm = sA + ATILE_B;
#pragma unroll
        for (int kk = 0; kk < BK; kk += 16) {
            uint32_t afr[4][4];
            uint32_t bfr[4][2];
#pragma unroll
            for (int mt = 0; mt < 4; mt++)
                ldsm4(afr[mt],
                      sA + (uint32_t)(((m0w + mt * 16 + a_row) * ROWP + kk + a_col) * 2));
#pragma unroll
            for (int np = 0; np < 2; np++) {
                uint32_t q[4];
                ldsm4(q, sBm + (uint32_t)(((n0w + np * 16 + b_row) * ROWP + kk + b_col) * 2));
                bfr[np * 2 + 0][0] = q[0]; bfr[np * 2 + 0][1] = q[1];
                bfr[np * 2 + 1][0] = q[2]; bfr[np * 2 + 1][1] = q[3];
            }
#pragma unroll
            for (int mt = 0; mt < 4; mt++)
#pragma unroll
                for (int nt = 0; nt < 4; nt++)
                    mma16816(c[mt][nt], afr[mt], bfr[nt]);
        }
    }

    const int er = lane >> 2;
    const int ec = (lane & 3) * 2;
#pragma unroll
    for (int mt = 0; mt < 4; mt++) {
#pragma unroll
        for (int nt = 0; nt < 4; nt++) {
            const int m = row0 + m0w + mt * 16 + er;
            const int n = col0 + n0w + nt * 8 + ec;
            const float b0 = __ldg(&bp[n]);
            const float b1 = __ldg(&bp[n + 1]);
            *reinterpret_cast<float2*>(&g_theta[(size_t)m * NTOT + n]) =
                make_float2(c[mt][nt][0] + b0, c[mt][nt][1] + b1);
            *reinterpret_cast<float2*>(&g_theta[(size_t)(m + 8) * NTOT + n]) =
                make_float2(c[mt][nt][2] + b0, c[mt][nt][3] + b1);
        }
    }
}

// ---------------------------------------------------------------------------
// Fused pair kernel: one block per b.
//   Phase A: z/Z, box side-products, concept probs (head fused in).
//   Pass 1:  intersection side-products over the (i<=j) triangle.
//   Pass 2:  cond = prod_int * (1/prod_box_j)  (no MUFU at all), + dots.
// ---------------------------------------------------------------------------
__device__ __forceinline__ float softplus_acc(float x) {
    return fmaxf(x, 0.0f) + log1pf(expf(-fabsf(x)));
}
__device__ __forceinline__ int tri_S(int i) { return (i * (129 - i)) >> 1; }

__global__ void __launch_bounds__(256) pair_kernel(const float* __restrict__ Wprob,
                                                   const float* __restrict__ bprob,
                                                   const float* __restrict__ Wrel,
                                                   const float* __restrict__ Wbox,
                                                   const float* __restrict__ bbox,
                                                   const float* __restrict__ brel,
                                                   float* __restrict__ out_concept,
                                                   float* __restrict__ out_cond,
                                                   float* __restrict__ out_task) {
    __shared__ float2 zZ[KC * 9];          // (z, Z) interleaved, stride-9 padded
    __shared__ float elvb[KC];             // exp(-lv_box) = 1 / prod(box sides)
    __shared__ float p_sh[KC];
    __shared__ float wrel_sh[KC * KC];
    __shared__ float wbox_sh[KC * 16];
    __shared__ float prod_sh[NPAIR];       // prod of intersection sides (= exp(lv_int))
    __shared__ float side_tmp[KC * DD];
    __shared__ float dot_tmp[KC * DD];
    __shared__ float red[256];

    const int b   = blockIdx.x;
    const int tid = threadIdx.x;

    for (int idx = tid; idx < KC * KC; idx += 256) wrel_sh[idx] = Wrel[idx];
    for (int idx = tid; idx < KC * 16; idx += 256) wbox_sh[idx] = Wbox[idx];

    // -------- phase A: z/Z + per-dim box sides + concept dot terms --------
    for (int u = tid; u < KC * DD; u += 256) {
        const int k = u >> 3, d = u & 7;
        const float* th = &g_theta[(size_t)b * NTOT + k * 16];
        const float z = th[d];
        const float Z = z + softplus_acc(th[8 + d]);
        zZ[k * 9 + d] = make_float2(z, Z);
        side_tmp[u] = fmaxf(0.5f * softplus_acc(2.0f * (Z - z)), EPSV);
        dot_tmp[u]  = z * __ldg(&Wprob[k * 16 + d]) + Z * __ldg(&Wprob[k * 16 + 8 + d]);
    }
    __syncthreads();

    if (tid < KC) {
        float pb = 1.0f;
        float lg = __ldg(&bprob[tid]);
#pragma unroll
        for (int d = 0; d < 8; d++) {
            pb *= side_tmp[tid * 8 + d];
            lg += dot_tmp[tid * 8 + d];
        }
        elvb[tid] = 1.0f / pb;
        const float p = 1.0f / (1.0f + expf(-lg));
        p_sh[tid] = p;
        out_concept[b * KC + tid] = p;
    }
    __syncthreads();

    // -------- pass 1: intersection side-products over triangle --------
    for (int q = tid; q < NPAIR; q += 256) {
        int i = (int)((129.0f - sqrtf((float)(16641 - 8 * q))) * 0.5f);
        while (i < 63 && tri_S(i + 1) <= q) i++;
        while (i > 0 && tri_S(i) > q) i--;
        const int j = i + (q - tri_S(i));

        float prod = 1.0f;
#pragma unroll
        for (int d = 0; d < 8; d++) {
            const float2 bi = zZ[i * 9 + d];
            const float2 bj = zZ[j * 9 + d];
            const float mz = fmaxf(bi.x, bj.x);
            const float dz = fabsf(bi.x - bj.x);
            const float mZ = fminf(bi.y, bj.y);
            const float dZ = fabsf(bi.y - bj.y);
            // z_int = mz + 0.1*log1p(ez); Z_int = mZ - 0.1*log1p(eZ)
            const float ez = __expf(-10.0f * dz);
            const float eZ = __expf(-10.0f * dZ);
            const float Lc = __logf((1.0f + ez) * (1.0f + eZ));   // merged logs
            const float w2 = 2.0f * (mZ - mz) - 0.2f * Lc;
            const float sp = fmaxf(w2, 0.0f) + __logf(1.0f + __expf(-fabsf(w2)));
            prod *= fmaxf(0.5f * sp, EPSV);
        }
        prod_sh[q] = prod;   // == exp(lv_int); underflow lands in the 1e-6 clip
    }
    __syncthreads();

    // -------- pass 2: cond + rel dot (pure FMA) --------
    float accrel = 0.0f;
    for (int idx = tid; idx < KC * KC; idx += 256) {
        const int i = idx >> 6, j = idx & 63;
        const int a  = (i < j) ? i : j;
        const int bb = (i < j) ? j : i;
        const int q  = tri_S(a) + (bb - a);
        float cd = prod_sh[q] * elvb[j];
        cd = fminf(fmaxf(cd, 1e-6f), 1.0f - 1e-6f);
        out_cond[(size_t)b * (KC * KC) + idx] = cd;
        accrel = fmaf(cd, wrel_sh[idx], accrel);
    }

    red[tid] = accrel;
    __syncthreads();
    for (int s = 128; s > 0; s >>= 1) {
        if (tid < s) red[tid] += red[tid + s];
        __syncthreads();
    }
    const float reldot = red[0];
    __syncthreads();

    if (tid < KC) {
        float s = 0.0f;
#pragma unroll
        for (int d = 0; d < 8; d++) {
            const float2 v = zZ[tid * 9 + d];
            s = fmaf(v.x, wbox_sh[tid * 16 + d], s);
            s = fmaf(v.y, wbox_sh[tid * 16 + 8 + d], s);
        }
        red[tid] = s * p_sh[tid];
    }
    __syncthreads();
    for (int s = 32; s > 0; s >>= 1) {
        if (tid < s) red[tid] += red[tid + s];
        __syncthreads();
    }

    if (tid == 0) {
        const float logit = red[0] + bbox[0] + reldot + brel[0];
        out_task[b] = 1.0f / (1.0f + expf(-logit));
    }
}

// ---------------------------------------------------------------------------
extern "C" void kernel_launch(void* const* d_in, const int* in_sizes, int n_in,
                              void* d_out, int out_size) {
    const float* features = (const float*)d_in[0];
    const float* Wp       = (const float*)d_in[1];
    const float* bp       = (const float*)d_in[2];
    const float* Wprob    = (const float*)d_in[3];
    const float* bprob    = (const float*)d_in[4];
    const float* Wbox     = (const float*)d_in[5];
    const float* bbox     = (const float*)d_in[6];
    const float* Wrel     = (const float*)d_in[7];
    const float* brel     = (const float*)d_in[8];

    float* out         = (float*)d_out;
    float* out_task    = out;
    float* out_concept = out + BSZ;
    float* out_cond    = out + BSZ + BSZ * KC;

    cudaFuncSetAttribute(gemm_hmma, cudaFuncAttributeMaxDynamicSharedMemorySize, SMEM_B);

    convA_kernel<<<(BSZ * (FDIM / 4) + 255) / 256, 256>>>(features);
    convB_kernel<<<(NTOT * (FDIM / 4) + 255) / 256, 256>>>(Wp);
    gemm_hmma<<<dim3(NTOT / TN, BSZ / TM), GT, SMEM_B>>>(bp);
    pair_kernel<<<BSZ, 256>>>(Wprob, bprob, Wrel, Wbox, bbox, brel,
                              out_concept, out_cond, out_task);
}

// round 7
// speedup vs baseline: 2.2834x; 1.2078x over previous
#include <cuda_runtime.h>
#include <cuda_bf16.h>
#include <math.h>
#include <stdint.h>

// ---------------- problem constants ----------------
#define BSZ   4096
#define FDIM  2048
#define KC    64
#define DD    8
#define NTOT  1024          // K * 2 * D
#define NPAIR 2080
#define NTILE 528           // 32*33/2 2x2 pair-tiles

// ---------------- GEMM config (bf16x3 split, mma.sync HMMA) ----------------
#define KEXP    6144        // logical K after 3-way split
#define KSTORE  4096        // physical K stored ([hi|lo]); region remap in loader
#define TM      128
#define TN      128
#define BK      64
#define NS      (KEXP / BK) // 96
#define STAGES  3
#define GT      256
#define ROWP    72          // padded row length in bf16 (144B: ldmatrix conflict-free)
#define ATILE_B (TM * ROWP * 2)          // 18432 bytes
#define STAGE_B (2 * ATILE_B)            // 36864 bytes
#define SMEM_B  (STAGES * STAGE_B)       // 110592 bytes

// (ln2/2)^8 : folds the 0.5*ln2 per-dim scale of side = 0.5*ln2*log2(1+E)
#define C8     2.0814397e-4f
#define C1EXP  (-14.4269504089f)   // -10 * log2(e)
#define C2EXP  (2.8853900818f)     //   2 * log2(e)

// ---------------- scratch ----------------
__device__ __nv_bfloat16 g_A[(size_t)BSZ * KSTORE];   // [4096][4096] = [Ahi|Alo]
__device__ __nv_bfloat16 g_Bm[(size_t)NTOT * KSTORE]; // [1024][4096] = [Whi|Wlo]
__device__ float g_theta[(size_t)BSZ * NTOT];

// ---------------- PTX helpers ----------------
__device__ __forceinline__ uint32_t smem_u32(const void* p) {
    uint32_t a;
    asm("{ .reg .u64 t; cvta.to.shared.u64 t, %1; cvt.u32.u64 %0, t; }"
        : "=r"(a) : "l"(p));
    return a;
}
__device__ __forceinline__ void cp_async16(uint32_t d, const void* s) {
    asm volatile("cp.async.cg.shared.global [%0], [%1], 16;" :: "r"(d), "l"(s));
}
#define CP_COMMIT() asm volatile("cp.async.commit_group;" ::: "memory")
template <int N> __device__ __forceinline__ void cp_wait() {
    asm volatile("cp.async.wait_group %0;" :: "n"(N) : "memory");
}
__device__ __forceinline__ void ldsm4(uint32_t* r, uint32_t addr) {
    asm volatile("ldmatrix.sync.aligned.m8n8.x4.shared.b16 {%0,%1,%2,%3}, [%4];"
                 : "=r"(r[0]), "=r"(r[1]), "=r"(r[2]), "=r"(r[3]) : "r"(addr));
}
__device__ __forceinline__ void mma16816(float* c, const uint32_t* a, const uint32_t* b) {
    asm volatile(
        "mma.sync.aligned.m16n8k16.row.col.f32.bf16.bf16.f32 "
        "{%0,%1,%2,%3}, {%4,%5,%6,%7}, {%8,%9}, {%0,%1,%2,%3};"
        : "+f"(c[0]), "+f"(c[1]), "+f"(c[2]), "+f"(c[3])
        : "r"(a[0]), "r"(a[1]), "r"(a[2]), "r"(a[3]), "r"(b[0]), "r"(b[1]));
}
__device__ __forceinline__ float ex2f(float x) {
    float y; asm("ex2.approx.ftz.f32 %0, %1;" : "=f"(y) : "f"(x)); return y;
}
__device__ __forceinline__ float lg2f(float x) {
    float y; asm("lg2.approx.ftz.f32 %0, %1;" : "=f"(y) : "f"(x)); return y;
}

// ---------------------------------------------------------------------------
// Conversion kernels: store only [hi | lo] halves; loader replays regions.
// Logical A'' = [Ahi | Alo | Ahi], B'' = [Whi | Whi | Wlo].
// ---------------------------------------------------------------------------
__global__ void __launch_bounds__(256) convA_kernel(const float* __restrict__ feat) {
    const int u = blockIdx.x * 256 + threadIdx.x;
    if (u >= BSZ * (FDIM / 4)) return;
    const int m = u >> 9;
    const int f = (u & 511) * 4;

    const float4 v = *reinterpret_cast<const float4*>(&feat[(size_t)m * FDIM + f]);
    union { __nv_bfloat16 h[4]; uint2 q; } Hi, Lo;
    Hi.h[0] = __float2bfloat16_rn(v.x);
    Hi.h[1] = __float2bfloat16_rn(v.y);
    Hi.h[2] = __float2bfloat16_rn(v.z);
    Hi.h[3] = __float2bfloat16_rn(v.w);
    Lo.h[0] = __float2bfloat16_rn(v.x - __bfloat162float(Hi.h[0]));
    Lo.h[1] = __float2bfloat16_rn(v.y - __bfloat162float(Hi.h[1]));
    Lo.h[2] = __float2bfloat16_rn(v.z - __bfloat162float(Hi.h[2]));
    Lo.h[3] = __float2bfloat16_rn(v.w - __bfloat162float(Hi.h[3]));

    __nv_bfloat16* row = &g_A[(size_t)m * KSTORE];
    *reinterpret_cast<uint2*>(&row[f])        = Hi.q;
    *reinterpret_cast<uint2*>(&row[FDIM + f]) = Lo.q;
}

__global__ void __launch_bounds__(256) convB_kernel(const float* __restrict__ Wp) {
    const int u = blockIdx.x * 256 + threadIdx.x;
    if (u >= NTOT * (FDIM / 4)) return;
    const int n = u >> 9;
    const int f = (u & 511) * 4;
    const int kbox = n >> 4;
    const int dd   = n & 15;

    union { __nv_bfloat16 h[4]; uint2 q; } Hi, Lo;
#pragma unroll
    for (int r = 0; r < 4; r++) {
        const float w = Wp[((size_t)kbox * FDIM + (f + r)) * 16 + dd];
        Hi.h[r] = __float2bfloat16_rn(w);
        Lo.h[r] = __float2bfloat16_rn(w - __bfloat162float(Hi.h[r]));
    }
    __nv_bfloat16* row = &g_Bm[(size_t)n * KSTORE];
    *reinterpret_cast<uint2*>(&row[f])        = Hi.q;
    *reinterpret_cast<uint2*>(&row[FDIM + f]) = Lo.q;
}

// ---------------------------------------------------------------------------
// HMMA GEMM: theta = A'' . B''^T + bp, 128x128 tile, BK=64, 3-stage cp.async.
// ---------------------------------------------------------------------------
__device__ __forceinline__ void load_stage(int tid, int t, uint32_t sb,
                                           const __nv_bfloat16* Ab,
                                           const __nv_bfloat16* Bb) {
    const int k0 = t * BK;
    const int ksA = (k0 < 2 * FDIM) ? k0 : k0 - 2 * FDIM;  // region 2 -> Ahi
    const int ksB = (k0 < FDIM) ? k0 : k0 - FDIM;          // regions 1,2 -> Whi,Wlo
    const uint32_t stage = sb + (uint32_t)((t % STAGES) * STAGE_B);
#pragma unroll
    for (int i = 0; i < 8; i++) {
        const int c = tid + i * GT;          // 0..2047 chunks of 16B
        if (c < 1024) {                      // A: 128 rows x 8 chunks
            const int row = c >> 3, seg = c & 7;
            cp_async16(stage + (uint32_t)(row * (ROWP * 2) + seg * 16),
                       Ab + (size_t)row * KSTORE + ksA + seg * 8);
        } else {                             // B: 128 rows x 8 chunks
            const int cc = c - 1024;
            const int row = cc >> 3, seg = cc & 7;
            cp_async16(stage + (uint32_t)(ATILE_B + row * (ROWP * 2) + seg * 16),
                       Bb + (size_t)row * KSTORE + ksB + seg * 8);
        }
    }
}

__global__ void __launch_bounds__(GT, 2) gemm_hmma(const float* __restrict__ bp) {
    extern __shared__ char smem[];
    const uint32_t sb = smem_u32(smem);
    const int tid  = threadIdx.x;
    const int wid  = tid >> 5;
    const int lane = tid & 31;
    const int row0 = blockIdx.y * TM;
    const int col0 = blockIdx.x * TN;
    const int m0w  = (wid >> 2) * 64;
    const int n0w  = (wid & 3) * 32;

    const __nv_bfloat16* Ab = g_A  + (size_t)row0 * KSTORE;
    const __nv_bfloat16* Bb = g_Bm + (size_t)col0 * KSTORE;

    float c[4][4][4];
#pragma unroll
    for (int mt = 0; mt < 4; mt++)
#pragma unroll
        for (int nt = 0; nt < 4; nt++)
#pragma unroll
            for (int r = 0; r < 4; r++) c[mt][nt][r] = 0.0f;

    const int a_row = lane & 15;
    const int a_col = (lane >> 4) * 8;
    const int b_row = (lane & 7) + ((lane >> 4) & 1) * 8;
    const int b_col = ((lane >> 3) & 1) * 8;

    load_stage(tid, 0, sb, Ab, Bb); CP_COMMIT();
    load_stage(tid, 1, sb, Ab, Bb); CP_COMMIT();

    for (int s = 0; s < NS; s++) {
        cp_wait<STAGES - 2>();
        __syncthreads();
        if (s + STAGES - 1 < NS) load_stage(tid, s + STAGES - 1, sb, Ab, Bb);
        CP_COMMIT();

        const uint32_t sA  = sb + (uint32_t)((s % STAGES) * STAGE_B);
        const uint32_t sBm = sA + ATILE_B;
#pragma unroll
        for (int kk = 0; kk < BK; kk += 16) {
            uint32_t afr[4][4];
            uint32_t bfr[4][2];
#pragma unroll
            for (int mt = 0; mt < 4; mt++)
                ldsm4(afr[mt],
                      sA + (uint32_t)(((m0w + mt * 16 + a_row) * ROWP + kk + a_col) * 2));
#pragma unroll
            for (int np = 0; np < 2; np++) {
                uint32_t q[4];
                ldsm4(q, sBm + (uint32_t)(((n0w + np * 16 + b_row) * ROWP + kk + b_col) * 2));
                bfr[np * 2 + 0][0] = q[0]; bfr[np * 2 + 0][1] = q[1];
                bfr[np * 2 + 1][0] = q[2]; bfr[np * 2 + 1][1] = q[3];
            }
#pragma unroll
            for (int mt = 0; mt < 4; mt++)
#pragma unroll
                for (int nt = 0; nt < 4; nt++)
                    mma16816(c[mt][nt], afr[mt], bfr[nt]);
        }
    }

    const int er = lane >> 2;
    const int ec = (lane & 3) * 2;
#pragma unroll
    for (int mt = 0; mt < 4; mt++) {
#pragma unroll
        for (int nt = 0; nt < 4; nt++) {
            const int m = row0 + m0w + mt * 16 + er;
            const int n = col0 + n0w + nt * 8 + ec;
            const float b0 = __ldg(&bp[n]);
            const float b1 = __ldg(&bp[n + 1]);
            *reinterpret_cast<float2*>(&g_theta[(size_t)m * NTOT + n]) =
                make_float2(c[mt][nt][0] + b0, c[mt][nt][1] + b1);
            *reinterpret_cast<float2*>(&g_theta[(size_t)(m + 8) * NTOT + n]) =
                make_float2(c[mt][nt][2] + b0, c[mt][nt][3] + b1);
        }
    }
}

// ---------------------------------------------------------------------------
// Fused pair kernel: one block per b.
// pass 1 works on 2x2 pair-tiles with register-resident boxes; all transcen-
// dentals in ex2/lg2 domain; per-dim scale (ln2/2) folded into elvbC.
// ---------------------------------------------------------------------------
__device__ __forceinline__ float sp_fast(float x) {
    return fmaxf(x, 0.0f) + __logf(1.0f + __expf(-fabsf(x)));
}
__device__ __forceinline__ int tri_S(int i) { return (i * (129 - i)) >> 1; }

// one dim: log2(1 + exp(w2)) with w2 = 2(mZ-mz) - 0.2*ln((1+u)(1+v))
__device__ __forceinline__ float dim1(float zi, float Zi, float zj, float Zj) {
    const float mz = fmaxf(zi, zj);
    const float mZ = fminf(Zi, Zj);
    const float u  = ex2f(C1EXP * fabsf(zi - zj));
    const float v  = ex2f(C1EXP * fabsf(Zi - Zj));
    const float L2 = lg2f((1.0f + u) * (1.0f + v));
    const float E  = ex2f(fmaf(mZ - mz, C2EXP, -0.2f * L2));
    return lg2f(1.0f + E);
}
__device__ __forceinline__ float quad(float4 zi, float4 Zi, float4 zj, float4 Zj) {
    return dim1(zi.x, Zi.x, zj.x, Zj.x) * dim1(zi.y, Zi.y, zj.y, Zj.y)
         * dim1(zi.z, Zi.z, zj.z, Zj.z) * dim1(zi.w, Zi.w, zj.w, Zj.w);
}
// full 8-dim product for one pair; box layout: [zlo, zhi, Zlo, Zhi] float4s
__device__ __forceinline__ float pairp(const float4* bi, const float4* bj) {
    return quad(bi[0], bi[2], bj[0], bj[2]) * quad(bi[1], bi[3], bj[1], bj[3]);
}

__global__ void __launch_bounds__(256) pair_kernel(const float* __restrict__ Wprob,
                                                   const float* __restrict__ bprob,
                                                   const float* __restrict__ Wrel,
                                                   const float* __restrict__ Wbox,
                                                   const float* __restrict__ bbox,
                                                   const float* __restrict__ brel,
                                                   float* __restrict__ out_concept,
                                                   float* __restrict__ out_cond,
                                                   float* __restrict__ out_task) {
    __shared__ float4 zZ4q[KC * 5];        // box k at [k*5 .. k*5+3], 1 f4 pad (banks)
    __shared__ float elvbC[KC];            // (ln2/2)^8 / prod(box sides)
    __shared__ float p_sh[KC];
    __shared__ float wrel_sh[KC * KC];
    __shared__ float wbox_sh[KC * 16];
    __shared__ float prod_sh[NPAIR];       // prod_d log2(1+E_d)
    __shared__ float side_tmp[KC * DD];
    __shared__ float dot_tmp[KC * DD];
    __shared__ float red[256];

    const int b   = blockIdx.x;
    const int tid = threadIdx.x;
    float* zZf = reinterpret_cast<float*>(zZ4q);

    for (int idx = tid; idx < KC * KC; idx += 256) wrel_sh[idx] = Wrel[idx];
    for (int idx = tid; idx < KC * 16; idx += 256) wbox_sh[idx] = Wbox[idx];

    // -------- phase A: z/Z + per-dim box sides + concept dot terms --------
    for (int u = tid; u < KC * DD; u += 256) {
        const int k = u >> 3, d = u & 7;
        const float* th = &g_theta[(size_t)b * NTOT + k * 16];
        const float z = th[d];
        const float Z = z + sp_fast(th[8 + d]);
        zZf[k * 20 + d]     = z;
        zZf[k * 20 + 8 + d] = Z;
        side_tmp[u] = 0.5f * sp_fast(2.0f * (Z - z));   // >= ln2/2, no clamp needed
        dot_tmp[u]  = z * __ldg(&Wprob[k * 16 + d]) + Z * __ldg(&Wprob[k * 16 + 8 + d]);
    }
    __syncthreads();

    if (tid < KC) {
        float pb = 1.0f;
        float lg = __ldg(&bprob[tid]);
#pragma unroll
        for (int d = 0; d < 8; d++) {
            pb *= side_tmp[tid * 8 + d];
            lg += dot_tmp[tid * 8 + d];
        }
        elvbC[tid] = C8 / pb;
        const float p = 1.0f / (1.0f + __expf(-lg));
        p_sh[tid] = p;
        out_concept[b * KC + tid] = p;
    }
    __syncthreads();

    // -------- pass 1: 2x2 pair-tiles over tile-triangle (528 tiles) --------
    for (int T = tid; T < NTILE; T += 256) {
        // rectangle->triangle bijection over C(33,2)
        const int tt = T / 33;                // 0..15
        const int s  = T - tt * 33;           // 0..32
        int b2 = s + tt + 1;
        if (b2 >= 33) b2 -= 33;
        const int lo = min(s, b2), hi = max(s, b2);
        const int i0 = lo * 2;
        const int j0 = (hi - 1) * 2;

        float4 BI0[4], BI1[4], BJ0[4], BJ1[4];
#pragma unroll
        for (int r = 0; r < 4; r++) {
            BI0[r] = zZ4q[(i0 + 0) * 5 + r];
            BI1[r] = zZ4q[(i0 + 1) * 5 + r];
            BJ0[r] = zZ4q[(j0 + 0) * 5 + r];
            BJ1[r] = zZ4q[(j0 + 1) * 5 + r];
        }

        const float p00 = pairp(BI0, BJ0);
        const float p01 = pairp(BI0, BJ1);
        const float p11 = pairp(BI1, BJ1);

        const int q0 = tri_S(i0) + (j0 - i0);
        const int q1 = tri_S(i0 + 1) + (j0 - i0 - 1);
        prod_sh[q0]     = p00;
        prod_sh[q0 + 1] = p01;
        prod_sh[q1 + 1] = p11;                 // (i0+1, j0+1)
        if (i0 < j0) {                         // off-diagonal tile: (i0+1, j0) valid
            prod_sh[q1] = pairp(BI1, BJ0);
        }
    }
    __syncthreads();

    // -------- pass 2: cond + rel dot, float4 stores --------
    float accrel = 0.0f;
#pragma unroll
    for (int g = 0; g < 4; g++) {
        const int idx = g * 1024 + tid * 4;
        const int i  = idx >> 6;
        const int jb = idx & 63;
        float4 cd;
        float* cdp = &cd.x;
#pragma unroll
        for (int r = 0; r < 4; r++) {
            const int j = jb + r;
            const int a = min(i, j), bq = max(i, j);
            const int q = tri_S(a) + (bq - a);
            float cc = prod_sh[q] * elvbC[j];
            cc = fminf(fmaxf(cc, 1e-6f), 1.0f - 1e-6f);
            cdp[r] = cc;
            accrel = fmaf(cc, wrel_sh[idx + r], accrel);
        }
        *reinterpret_cast<float4*>(&out_cond[(size_t)b * (KC * KC) + idx]) = cd;
    }

    red[tid] = accrel;
    __syncthreads();
    for (int s = 128; s > 0; s >>= 1) {
        if (tid < s) red[tid] += red[tid + s];
        __syncthreads();
    }
    const float reldot = red[0];
    __syncthreads();

    if (tid < KC) {
        float s = 0.0f;
#pragma unroll
        for (int d = 0; d < 8; d++) {
            s = fmaf(zZf[tid * 20 + d],     wbox_sh[tid * 16 + d],     s);
            s = fmaf(zZf[tid * 20 + 8 + d], wbox_sh[tid * 16 + 8 + d], s);
        }
        red[tid] = s * p_sh[tid];
    }
    __syncthreads();
    for (int s = 32; s > 0; s >>= 1) {
        if (tid < s) red[tid] += red[tid + s];
        __syncthreads();
    }

    if (tid == 0) {
        const float logit = red[0] + bbox[0] + reldot + brel[0];
        out_task[b] = 1.0f / (1.0f + expf(-logit));
    }
}

// ---------------------------------------------------------------------------
extern "C" void kernel_launch(void* const* d_in, const int* in_sizes, int n_in,
                              void* d_out, int out_size) {
    const float* features = (const float*)d_in[0];
    const float* Wp       = (const float*)d_in[1];
    const float* bp       = (const float*)d_in[2];
    const float* Wprob    = (const float*)d_in[3];
    const float* bprob    = (const float*)d_in[4];
    const float* Wbox     = (const float*)d_in[5];
    const float* bbox     = (const float*)d_in[6];
    const float* Wrel     = (const float*)d_in[7];
    const float* brel     = (const float*)d_in[8];

    float* out         = (float*)d_out;
    float* out_task    = out;
    float* out_concept = out + BSZ;
    float* out_cond    = out + BSZ + BSZ * KC;

    cudaFuncSetAttribute(gemm_hmma, cudaFuncAttributeMaxDynamicSharedMemorySize, SMEM_B);

    convA_kernel<<<(BSZ * (FDIM / 4) + 255) / 256, 256>>>(features);
    convB_kernel<<<(NTOT * (FDIM / 4) + 255) / 256, 256>>>(Wp);
    gemm_hmma<<<dim3(NTOT / TN, BSZ / TM), GT, SMEM_B>>>(bp);
    pair_kernel<<<BSZ, 256>>>(Wprob, bprob, Wrel, Wbox, bbox, brel,
                              out_concept, out_cond, out_task);
}